// round 15
// baseline (speedup 1.0000x reference)
#include <cuda_runtime.h>
#include <stdint.h>

// Problem constants (fixed by the dataset)
#define D_IN   256
#define D_OUT  128
#define MAXN   100352          // >= N=100000, padded
#define LEAKY  0.2f
#define EPS    1e-3f

// GEMM tiling
#define TM 128
#define TN 128
#define TK 16
#define ASTR 132               // padded A-smem stride (multiple of 4 for float4 reads)

// ---------------- device scratch (static: allocation-guard compliant) ----------------
__device__ float g_part[256 * 512];            // BN partial sums: 256 blocks x (sum[256], sq[256])
__device__ float g_mean[D_IN];
__device__ float g_rstd[D_IN];
__device__ float g_xn[(size_t)MAXN * D_IN];    // normalized x, ~103 MB
__device__ float g_mapped[(size_t)MAXN * D_OUT]; // xn @ w, ~51 MB
__device__ float g_spart[4 * MAXN];            // quadratic-form partial dots
__device__ float g_s1[MAXN];
__device__ float g_s2[MAXN];
__device__ int   g_rowptr[MAXN + 1];

// packed f32x2 FMA (ptxas never emits FFMA2 from C++; PTX-only path, 2x issue throughput)
#define FMA2(c, a, b) asm("fma.rn.f32x2 %0, %1, %2, %0;" : "+l"(c) : "l"(a), "l"(b))

// ---------------- 1. BatchNorm partial stats ----------------
__global__ void bn_partial_kernel(const float* __restrict__ x, int N) {
    const int k = threadIdx.x;                 // feature 0..255
    const int per = (N + gridDim.x - 1) / gridDim.x;
    int r0 = blockIdx.x * per;
    int r1 = r0 + per; if (r1 > N) r1 = N;
    float s = 0.f, q = 0.f;
#pragma unroll 4
    for (int r = r0; r < r1; r++) {
        float v = x[(size_t)r * D_IN + k];
        s += v; q += v * v;
    }
    g_part[blockIdx.x * 512 + k]       = s;
    g_part[blockIdx.x * 512 + 256 + k] = q;
}

// ---------------- 2. BN finalize: mean, rstd ----------------
__global__ void bn_final_kernel(int N, int nblocks) {
    const int k = threadIdx.x;
    float s = 0.f, q = 0.f;
    for (int b = 0; b < nblocks; b++) {
        s += g_part[b * 512 + k];
        q += g_part[b * 512 + 256 + k];
    }
    float mean = s / (float)N;
    float var  = q / (float)N - mean * mean;
    g_mean[k] = mean;
    g_rstd[k] = 1.0f / sqrtf(var + EPS);
}

// ---------------- 3. normalize: xn = (x - mean) * rstd ----------------
__global__ void normalize_kernel(const float* __restrict__ x, int n4) {
    int i = blockIdx.x * blockDim.x + threadIdx.x;
    if (i >= n4) return;
    float4 v = ((const float4*)x)[i];
    int k = (i & 63) << 2;                     // feature index of .x
    v.x = (v.x - g_mean[k + 0]) * g_rstd[k + 0];
    v.y = (v.y - g_mean[k + 1]) * g_rstd[k + 1];
    v.z = (v.z - g_mean[k + 2]) * g_rstd[k + 2];
    v.w = (v.w - g_mean[k + 3]) * g_rstd[k + 3];
    ((float4*)g_xn)[i] = v;
}

// ---------------- 4. fused GEMM: mapped + quadratic-form partials ----------------
// blockIdx.y (ct): 0 -> xn@w  (writes g_mapped)
//                  1 -> xn@w1 cols[0:128)   -> spart[0]
//                  2 -> xn@w1 cols[128:256) -> spart[1]
//                  3 -> xn@w2 cols[0:128)   -> spart[2]
//                  4 -> xn@w2 cols[128:256) -> spart[3]
__global__ __launch_bounds__(256)
void gemm_kernel(const float* __restrict__ w, const float* __restrict__ w1,
                 const float* __restrict__ w2, int N)
{
    __shared__ __align__(16) float As[2][TK][ASTR];
    __shared__ __align__(16) float Bs[2][TK][TN];
    __shared__ float red[TM][17];

    const int ct = blockIdx.y;
    const int rowbase = blockIdx.x * TM;
    const int tid = threadIdx.x;
    const int tx = tid & 15, ty = tid >> 4;

    const float* Bp; int ldb, bcol;
    switch (ct) {
        case 0:  Bp = w;  ldb = D_OUT; bcol = 0;   break;
        case 1:  Bp = w1; ldb = D_IN;  bcol = 0;   break;
        case 2:  Bp = w1; ldb = D_IN;  bcol = 128; break;
        case 3:  Bp = w2; ldb = D_IN;  bcol = 0;   break;
        default: Bp = w2; ldb = D_IN;  bcol = 128; break;
    }

    // A-load: each thread loads 2 float4 (rows tid>>2 and +64, k-quad (tid&3)*4)
    const int a_r0 = tid >> 2;
    const int a_r1 = a_r0 + 64;
    const int a_k  = (tid & 3) << 2;
    const int gr0 = rowbase + a_r0;
    const int gr1 = rowbase + a_r1;
    // B-load: each thread loads 2 float4 (k rows tid>>5 and +8, col-quad (tid&31)*4)
    const int b_k0 = tid >> 5;
    const int b_k1 = b_k0 + 8;
    const int b_c  = (tid & 31) << 2;

    unsigned long long acc[8][4];
#pragma unroll
    for (int i = 0; i < 8; i++)
#pragma unroll
        for (int p = 0; p < 4; p++) acc[i][p] = 0ull;

    const float4 zero4 = make_float4(0.f, 0.f, 0.f, 0.f);
    float4 av0, av1, bv0, bv1;

    // prefetch tile 0
    av0 = (gr0 < N) ? *(const float4*)(g_xn + (size_t)gr0 * D_IN + a_k) : zero4;
    av1 = (gr1 < N) ? *(const float4*)(g_xn + (size_t)gr1 * D_IN + a_k) : zero4;
    bv0 = *(const float4*)(Bp + (size_t)b_k0 * ldb + bcol + b_c);
    bv1 = *(const float4*)(Bp + (size_t)b_k1 * ldb + bcol + b_c);
    {
        float t0[4] = {av0.x, av0.y, av0.z, av0.w};
        float t1[4] = {av1.x, av1.y, av1.z, av1.w};
#pragma unroll
        for (int q = 0; q < 4; q++) { As[0][a_k + q][a_r0] = t0[q]; As[0][a_k + q][a_r1] = t1[q]; }
        *(float4*)&Bs[0][b_k0][b_c] = bv0;
        *(float4*)&Bs[0][b_k1][b_c] = bv1;
    }
    __syncthreads();

    const int NKT = D_IN / TK;                 // 16
    for (int kt = 0; kt < NKT; kt++) {
        const int buf = kt & 1;
        if (kt + 1 < NKT) {
            const int koff = (kt + 1) * TK;
            av0 = (gr0 < N) ? *(const float4*)(g_xn + (size_t)gr0 * D_IN + koff + a_k) : zero4;
            av1 = (gr1 < N) ? *(const float4*)(g_xn + (size_t)gr1 * D_IN + koff + a_k) : zero4;
            bv0 = *(const float4*)(Bp + (size_t)(koff + b_k0) * ldb + bcol + b_c);
            bv1 = *(const float4*)(Bp + (size_t)(koff + b_k1) * ldb + bcol + b_c);
        }
#pragma unroll
        for (int k = 0; k < TK; k++) {
            float4 a0 = *(const float4*)&As[buf][k][ty * 8];
            float4 a1 = *(const float4*)&As[buf][k][ty * 8 + 4];
            const unsigned long long* bp = (const unsigned long long*)&Bs[buf][k][tx * 8];
            unsigned long long b0 = bp[0], b1 = bp[1], b2 = bp[2], b3 = bp[3];
            float av[8] = {a0.x, a0.y, a0.z, a0.w, a1.x, a1.y, a1.z, a1.w};
#pragma unroll
            for (int i = 0; i < 8; i++) {
                unsigned long long a2;
                unsigned int au = __float_as_uint(av[i]);
                asm("mov.b64 %0, {%1, %1};" : "=l"(a2) : "r"(au));
                FMA2(acc[i][0], a2, b0);
                FMA2(acc[i][1], a2, b1);
                FMA2(acc[i][2], a2, b2);
                FMA2(acc[i][3], a2, b3);
            }
        }
        if (kt + 1 < NKT) {
            const int nb = buf ^ 1;
            float t0[4] = {av0.x, av0.y, av0.z, av0.w};
            float t1[4] = {av1.x, av1.y, av1.z, av1.w};
#pragma unroll
            for (int q = 0; q < 4; q++) { As[nb][a_k + q][a_r0] = t0[q]; As[nb][a_k + q][a_r1] = t1[q]; }
            *(float4*)&Bs[nb][b_k0][b_c] = bv0;
            *(float4*)&Bs[nb][b_k1][b_c] = bv1;
        }
        __syncthreads();
    }

    // unpack accumulators
    float c[8][8];
#pragma unroll
    for (int i = 0; i < 8; i++)
#pragma unroll
        for (int p = 0; p < 4; p++) {
            unsigned int lo, hi;
            asm("mov.b64 {%0, %1}, %2;" : "=r"(lo), "=r"(hi) : "l"(acc[i][p]));
            c[i][2 * p]     = __uint_as_float(lo);
            c[i][2 * p + 1] = __uint_as_float(hi);
        }

    if (ct == 0) {
#pragma unroll
        for (int i = 0; i < 8; i++) {
            const int r = rowbase + ty * 8 + i;
            if (r < N) {
                float* op = g_mapped + (size_t)r * D_OUT + tx * 8;
                *(float4*)op       = make_float4(c[i][0], c[i][1], c[i][2], c[i][3]);
                *(float4*)(op + 4) = make_float4(c[i][4], c[i][5], c[i][6], c[i][7]);
            }
        }
    } else {
        const int xoff = ((ct - 1) & 1) * 128;     // xn column offset this col-tile multiplies
#pragma unroll
        for (int i = 0; i < 8; i++) {
            const int r = rowbase + ty * 8 + i;
            float d = 0.f;
            if (r < N) {
                const float4* xp = (const float4*)(g_xn + (size_t)r * D_IN + xoff + tx * 8);
                float4 x0 = xp[0], x1 = xp[1];
                d = c[i][0] * x0.x + c[i][1] * x0.y + c[i][2] * x0.z + c[i][3] * x0.w
                  + c[i][4] * x1.x + c[i][5] * x1.y + c[i][6] * x1.z + c[i][7] * x1.w;
            }
            red[ty * 8 + i][tx] = d;
        }
        __syncthreads();
        if (tid < TM) {
            float s = 0.f;
#pragma unroll
            for (int j = 0; j < 16; j++) s += red[tid][j];
            const int r = rowbase + tid;
            if (r < N) g_spart[(ct - 1) * MAXN + r] = s;
        }
    }
}

// ---------------- 5. combine quadratic-form halves -> tanh scores ----------------
__global__ void combine_kernel(int N) {
    int i = blockIdx.x * blockDim.x + threadIdx.x;
    if (i >= N) return;
    g_s1[i] = tanhf(g_spart[i]            + g_spart[MAXN + i]);
    g_s2[i] = tanhf(g_spart[2 * MAXN + i] + g_spart[3 * MAXN + i]);
}

// ---------------- 6. row_ptr via binary search (rows sorted) ----------------
__global__ void rowptr_kernel(const int* __restrict__ rows, int N, int E) {
    int i = blockIdx.x * blockDim.x + threadIdx.x;
    if (i > N) return;
    int lo = 0, hi = E;
    while (lo < hi) {
        int mid = (lo + hi) >> 1;
        if (rows[mid] < i) lo = mid + 1; else hi = mid;
    }
    g_rowptr[i] = lo;
}

// ---------------- 7. edge softmax + SpMM: warp per node ----------------
__global__ __launch_bounds__(256)
void attn_kernel(const int* __restrict__ cols, const float* __restrict__ evals,
                 float* __restrict__ out, int N)
{
    const int node = (blockIdx.x * blockDim.x + threadIdx.x) >> 5;
    const int lane = threadIdx.x & 31;
    if (node >= N) return;

    const int start = g_rowptr[node];
    const int end   = g_rowptr[node + 1];
    float4 acc = make_float4(0.f, 0.f, 0.f, 0.f);

    if (start < end) {
        const float s1r = g_s1[node];
        // pass 1: segment max of leaky(ev)
        float m = -1e30f;
        for (int e = start + lane; e < end; e += 32) {
            float ev = evals[e] * (s1r + g_s2[cols[e]]);
            ev = ev > 0.f ? ev : LEAKY * ev;
            m = fmaxf(m, ev);
        }
#pragma unroll
        for (int o = 16; o; o >>= 1) m = fmaxf(m, __shfl_xor_sync(0xffffffffu, m, o));
        // pass 2: denom
        float dsum = 0.f;
        for (int e = start + lane; e < end; e += 32) {
            float ev = evals[e] * (s1r + g_s2[cols[e]]);
            ev = ev > 0.f ? ev : LEAKY * ev;
            dsum += __expf(ev - m);
        }
#pragma unroll
        for (int o = 16; o; o >>= 1) dsum += __shfl_xor_sync(0xffffffffu, dsum, o);
        const float rinv = 1.0f / dsum;
        // pass 3: SpMM accumulate (lane covers features lane*4 .. lane*4+3)
        for (int e = start; e < end; e++) {
            const int ccol = cols[e];                  // broadcast load
            float ev = evals[e] * (s1r + g_s2[ccol]);
            ev = ev > 0.f ? ev : LEAKY * ev;
            const float alpha = __expf(ev - m) * rinv;
            float4 mv = *(const float4*)(g_mapped + (size_t)ccol * D_OUT + lane * 4);
            acc.x += alpha * mv.x; acc.y += alpha * mv.y;
            acc.z += alpha * mv.z; acc.w += alpha * mv.w;
        }
    }
    *(float4*)(out + (size_t)node * D_OUT + lane * 4) = acc;   // empty rows -> zeros
}

// ---------------- launch ----------------
extern "C" void kernel_launch(void* const* d_in, const int* in_sizes, int n_in,
                              void* d_out, int out_size)
{
    const float* x     = (const float*)d_in[0];
    const float* w     = (const float*)d_in[1];
    const float* w1    = (const float*)d_in[2];
    const float* w2    = (const float*)d_in[3];
    const float* evals = (const float*)d_in[4];
    const int*   rows  = (const int*)d_in[5];
    const int*   cols  = (const int*)d_in[6];
    float* out = (float*)d_out;

    const int N = in_sizes[0] / D_IN;
    const int E = in_sizes[4];

    bn_partial_kernel<<<256, 256>>>(x, N);
    bn_final_kernel<<<1, 256>>>(N, 256);

    const int n4 = N * (D_IN / 4);
    normalize_kernel<<<(n4 + 255) / 256, 256>>>(x, n4);

    dim3 gg((N + TM - 1) / TM, 5);
    gemm_kernel<<<gg, 256>>>(w, w1, w2, N);

    combine_kernel<<<(N + 255) / 256, 256>>>(N);
    rowptr_kernel<<<(N + 1 + 255) / 256, 256>>>(rows, N, E);

    const long long threads = (long long)N * 32;
    attn_kernel<<<(unsigned)((threads + 255) / 256), 256>>>(cols, evals, out, N);
}

// round 16
// speedup vs baseline: 1.0021x; 1.0021x over previous
#include <cuda_runtime.h>
#include <stdint.h>

// Problem constants (fixed by the dataset)
#define D_IN   256
#define D_OUT  128
#define MAXN   100352          // >= N=100000, padded
#define LEAKY  0.2f
#define EPS    1e-3f

// GEMM tiling
#define TM 128
#define TN 128
#define TK 16
#define ASTR 132               // padded A-smem stride (multiple of 4 for float4 reads)

// ---------------- device scratch (static: allocation-guard compliant) ----------------
__device__ float g_part[256 * 512];            // BN partial sums: 256 blocks x (sum[256], sq[256])
__device__ float g_mean[D_IN];
__device__ float g_rstd[D_IN];
__device__ float g_xn[(size_t)MAXN * D_IN];    // normalized x, ~103 MB
__device__ float g_mapped[(size_t)MAXN * D_OUT]; // xn @ w, ~51 MB
__device__ float g_spart[4 * MAXN];            // quadratic-form partial dots
__device__ float g_s1[MAXN];
__device__ float g_s2[MAXN];
__device__ int   g_rowptr[MAXN + 1];

// packed f32x2 FMA (ptxas never emits FFMA2 from C++; PTX-only path, 2x issue throughput)
#define FMA2(c, a, b) asm("fma.rn.f32x2 %0, %1, %2, %0;" : "+l"(c) : "l"(a), "l"(b))

// ---------------- 1. BatchNorm partial stats ----------------
__global__ void bn_partial_kernel(const float* __restrict__ x, int N) {
    const int k = threadIdx.x;                 // feature 0..255
    const int per = (N + gridDim.x - 1) / gridDim.x;
    int r0 = blockIdx.x * per;
    int r1 = r0 + per; if (r1 > N) r1 = N;
    float s = 0.f, q = 0.f;
#pragma unroll 4
    for (int r = r0; r < r1; r++) {
        float v = x[(size_t)r * D_IN + k];
        s += v; q += v * v;
    }
    g_part[blockIdx.x * 512 + k]       = s;
    g_part[blockIdx.x * 512 + 256 + k] = q;
}

// ---------------- 2. BN finalize: mean, rstd ----------------
__global__ void bn_final_kernel(int N, int nblocks) {
    const int k = threadIdx.x;
    float s = 0.f, q = 0.f;
    for (int b = 0; b < nblocks; b++) {
        s += g_part[b * 512 + k];
        q += g_part[b * 512 + 256 + k];
    }
    float mean = s / (float)N;
    float var  = q / (float)N - mean * mean;
    g_mean[k] = mean;
    g_rstd[k] = 1.0f / sqrtf(var + EPS);
}

// ---------------- 3. normalize: xn = (x - mean) * rstd ----------------
__global__ void normalize_kernel(const float* __restrict__ x, int n4) {
    int i = blockIdx.x * blockDim.x + threadIdx.x;
    if (i >= n4) return;
    float4 v = ((const float4*)x)[i];
    int k = (i & 63) << 2;                     // feature index of .x
    v.x = (v.x - g_mean[k + 0]) * g_rstd[k + 0];
    v.y = (v.y - g_mean[k + 1]) * g_rstd[k + 1];
    v.z = (v.z - g_mean[k + 2]) * g_rstd[k + 2];
    v.w = (v.w - g_mean[k + 3]) * g_rstd[k + 3];
    ((float4*)g_xn)[i] = v;
}

// ---------------- 4. fused GEMM: mapped + quadratic-form partials ----------------
// blockIdx.y (ct): 0 -> xn@w  (writes g_mapped)
//                  1 -> xn@w1 cols[0:128)   -> spart[0]
//                  2 -> xn@w1 cols[128:256) -> spart[1]
//                  3 -> xn@w2 cols[0:128)   -> spart[2]
//                  4 -> xn@w2 cols[128:256) -> spart[3]
__global__ __launch_bounds__(256)
void gemm_kernel(const float* __restrict__ w, const float* __restrict__ w1,
                 const float* __restrict__ w2, int N)
{
    __shared__ __align__(16) float As[2][TK][ASTR];
    __shared__ __align__(16) float Bs[2][TK][TN];
    __shared__ float red[TM][17];

    const int ct = blockIdx.y;
    const int rowbase = blockIdx.x * TM;
    const int tid = threadIdx.x;
    const int tx = tid & 15, ty = tid >> 4;

    const float* Bp; int ldb, bcol;
    switch (ct) {
        case 0:  Bp = w;  ldb = D_OUT; bcol = 0;   break;
        case 1:  Bp = w1; ldb = D_IN;  bcol = 0;   break;
        case 2:  Bp = w1; ldb = D_IN;  bcol = 128; break;
        case 3:  Bp = w2; ldb = D_IN;  bcol = 0;   break;
        default: Bp = w2; ldb = D_IN;  bcol = 128; break;
    }

    // A-load: each thread loads 2 float4 (rows tid>>2 and +64, k-quad (tid&3)*4)
    const int a_r0 = tid >> 2;
    const int a_r1 = a_r0 + 64;
    const int a_k  = (tid & 3) << 2;
    const int gr0 = rowbase + a_r0;
    const int gr1 = rowbase + a_r1;
    // B-load: each thread loads 2 float4 (k rows tid>>5 and +8, col-quad (tid&31)*4)
    const int b_k0 = tid >> 5;
    const int b_k1 = b_k0 + 8;
    const int b_c  = (tid & 31) << 2;

    unsigned long long acc[8][4];
#pragma unroll
    for (int i = 0; i < 8; i++)
#pragma unroll
        for (int p = 0; p < 4; p++) acc[i][p] = 0ull;

    const float4 zero4 = make_float4(0.f, 0.f, 0.f, 0.f);
    float4 av0, av1, bv0, bv1;

    // prefetch tile 0
    av0 = (gr0 < N) ? *(const float4*)(g_xn + (size_t)gr0 * D_IN + a_k) : zero4;
    av1 = (gr1 < N) ? *(const float4*)(g_xn + (size_t)gr1 * D_IN + a_k) : zero4;
    bv0 = *(const float4*)(Bp + (size_t)b_k0 * ldb + bcol + b_c);
    bv1 = *(const float4*)(Bp + (size_t)b_k1 * ldb + bcol + b_c);
    {
        float t0[4] = {av0.x, av0.y, av0.z, av0.w};
        float t1[4] = {av1.x, av1.y, av1.z, av1.w};
#pragma unroll
        for (int q = 0; q < 4; q++) { As[0][a_k + q][a_r0] = t0[q]; As[0][a_k + q][a_r1] = t1[q]; }
        *(float4*)&Bs[0][b_k0][b_c] = bv0;
        *(float4*)&Bs[0][b_k1][b_c] = bv1;
    }
    __syncthreads();

    const int NKT = D_IN / TK;                 // 16
    for (int kt = 0; kt < NKT; kt++) {
        const int buf = kt & 1;
        if (kt + 1 < NKT) {
            const int koff = (kt + 1) * TK;
            av0 = (gr0 < N) ? *(const float4*)(g_xn + (size_t)gr0 * D_IN + koff + a_k) : zero4;
            av1 = (gr1 < N) ? *(const float4*)(g_xn + (size_t)gr1 * D_IN + koff + a_k) : zero4;
            bv0 = *(const float4*)(Bp + (size_t)(koff + b_k0) * ldb + bcol + b_c);
            bv1 = *(const float4*)(Bp + (size_t)(koff + b_k1) * ldb + bcol + b_c);
        }
#pragma unroll
        for (int k = 0; k < TK; k++) {
            float4 a0 = *(const float4*)&As[buf][k][ty * 8];
            float4 a1 = *(const float4*)&As[buf][k][ty * 8 + 4];
            const unsigned long long* bp = (const unsigned long long*)&Bs[buf][k][tx * 8];
            unsigned long long b0 = bp[0], b1 = bp[1], b2 = bp[2], b3 = bp[3];
            float av[8] = {a0.x, a0.y, a0.z, a0.w, a1.x, a1.y, a1.z, a1.w};
#pragma unroll
            for (int i = 0; i < 8; i++) {
                unsigned long long a2;
                unsigned int au = __float_as_uint(av[i]);
                asm("mov.b64 %0, {%1, %1};" : "=l"(a2) : "r"(au));
                FMA2(acc[i][0], a2, b0);
                FMA2(acc[i][1], a2, b1);
                FMA2(acc[i][2], a2, b2);
                FMA2(acc[i][3], a2, b3);
            }
        }
        if (kt + 1 < NKT) {
            const int nb = buf ^ 1;
            float t0[4] = {av0.x, av0.y, av0.z, av0.w};
            float t1[4] = {av1.x, av1.y, av1.z, av1.w};
#pragma unroll
            for (int q = 0; q < 4; q++) { As[nb][a_k + q][a_r0] = t0[q]; As[nb][a_k + q][a_r1] = t1[q]; }
            *(float4*)&Bs[nb][b_k0][b_c] = bv0;
            *(float4*)&Bs[nb][b_k1][b_c] = bv1;
        }
        __syncthreads();
    }

    // unpack accumulators
    float c[8][8];
#pragma unroll
    for (int i = 0; i < 8; i++)
#pragma unroll
        for (int p = 0; p < 4; p++) {
            unsigned int lo, hi;
            asm("mov.b64 {%0, %1}, %2;" : "=r"(lo), "=r"(hi) : "l"(acc[i][p]));
            c[i][2 * p]     = __uint_as_float(lo);
            c[i][2 * p + 1] = __uint_as_float(hi);
        }

    if (ct == 0) {
#pragma unroll
        for (int i = 0; i < 8; i++) {
            const int r = rowbase + ty * 8 + i;
            if (r < N) {
                float* op = g_mapped + (size_t)r * D_OUT + tx * 8;
                *(float4*)op       = make_float4(c[i][0], c[i][1], c[i][2], c[i][3]);
                *(float4*)(op + 4) = make_float4(c[i][4], c[i][5], c[i][6], c[i][7]);
            }
        }
    } else {
        const int xoff = ((ct - 1) & 1) * 128;     // xn column offset this col-tile multiplies
#pragma unroll
        for (int i = 0; i < 8; i++) {
            const int r = rowbase + ty * 8 + i;
            float d = 0.f;
            if (r < N) {
                const float4* xp = (const float4*)(g_xn + (size_t)r * D_IN + xoff + tx * 8);
                float4 x0 = xp[0], x1 = xp[1];
                d = c[i][0] * x0.x + c[i][1] * x0.y + c[i][2] * x0.z + c[i][3] * x0.w
                  + c[i][4] * x1.x + c[i][5] * x1.y + c[i][6] * x1.z + c[i][7] * x1.w;
            }
            red[ty * 8 + i][tx] = d;
        }
        __syncthreads();
        if (tid < TM) {
            float s = 0.f;
#pragma unroll
            for (int j = 0; j < 16; j++) s += red[tid][j];
            const int r = rowbase + tid;
            if (r < N) g_spart[(ct - 1) * MAXN + r] = s;
        }
    }
}

// ---------------- 5. combine quadratic-form halves -> tanh scores ----------------
__global__ void combine_kernel(int N) {
    int i = blockIdx.x * blockDim.x + threadIdx.x;
    if (i >= N) return;
    g_s1[i] = tanhf(g_spart[i]            + g_spart[MAXN + i]);
    g_s2[i] = tanhf(g_spart[2 * MAXN + i] + g_spart[3 * MAXN + i]);
}

// ---------------- 6. row_ptr via binary search (rows sorted) ----------------
__global__ void rowptr_kernel(const int* __restrict__ rows, int N, int E) {
    int i = blockIdx.x * blockDim.x + threadIdx.x;
    if (i > N) return;
    int lo = 0, hi = E;
    while (lo < hi) {
        int mid = (lo + hi) >> 1;
        if (rows[mid] < i) lo = mid + 1; else hi = mid;
    }
    g_rowptr[i] = lo;
}

// ---------------- 7. edge softmax + SpMM: warp per node ----------------
__global__ __launch_bounds__(256)
void attn_kernel(const int* __restrict__ cols, const float* __restrict__ evals,
                 float* __restrict__ out, int N)
{
    const int node = (blockIdx.x * blockDim.x + threadIdx.x) >> 5;
    const int lane = threadIdx.x & 31;
    if (node >= N) return;

    const int start = g_rowptr[node];
    const int end   = g_rowptr[node + 1];
    float4 acc = make_float4(0.f, 0.f, 0.f, 0.f);

    if (start < end) {
        const float s1r = g_s1[node];
        // pass 1: segment max of leaky(ev)
        float m = -1e30f;
        for (int e = start + lane; e < end; e += 32) {
            float ev = evals[e] * (s1r + g_s2[cols[e]]);
            ev = ev > 0.f ? ev : LEAKY * ev;
            m = fmaxf(m, ev);
        }
#pragma unroll
        for (int o = 16; o; o >>= 1) m = fmaxf(m, __shfl_xor_sync(0xffffffffu, m, o));
        // pass 2: denom
        float dsum = 0.f;
        for (int e = start + lane; e < end; e += 32) {
            float ev = evals[e] * (s1r + g_s2[cols[e]]);
            ev = ev > 0.f ? ev : LEAKY * ev;
            dsum += __expf(ev - m);
        }
#pragma unroll
        for (int o = 16; o; o >>= 1) dsum += __shfl_xor_sync(0xffffffffu, dsum, o);
        const float rinv = 1.0f / dsum;
        // pass 3: SpMM accumulate (lane covers features lane*4 .. lane*4+3)
        for (int e = start; e < end; e++) {
            const int ccol = cols[e];                  // broadcast load
            float ev = evals[e] * (s1r + g_s2[ccol]);
            ev = ev > 0.f ? ev : LEAKY * ev;
            const float alpha = __expf(ev - m) * rinv;
            float4 mv = *(const float4*)(g_mapped + (size_t)ccol * D_OUT + lane * 4);
            acc.x += alpha * mv.x; acc.y += alpha * mv.y;
            acc.z += alpha * mv.z; acc.w += alpha * mv.w;
        }
    }
    *(float4*)(out + (size_t)node * D_OUT + lane * 4) = acc;   // empty rows -> zeros
}

// ---------------- launch ----------------
extern "C" void kernel_launch(void* const* d_in, const int* in_sizes, int n_in,
                              void* d_out, int out_size)
{
    const float* x     = (const float*)d_in[0];
    const float* w     = (const float*)d_in[1];
    const float* w1    = (const float*)d_in[2];
    const float* w2    = (const float*)d_in[3];
    const float* evals = (const float*)d_in[4];
    const int*   rows  = (const int*)d_in[5];
    const int*   cols  = (const int*)d_in[6];
    float* out = (float*)d_out;

    const int N = in_sizes[0] / D_IN;
    const int E = in_sizes[4];

    bn_partial_kernel<<<256, 256>>>(x, N);
    bn_final_kernel<<<1, 256>>>(N, 256);

    const int n4 = N * (D_IN / 4);
    normalize_kernel<<<(n4 + 255) / 256, 256>>>(x, n4);

    dim3 gg((N + TM - 1) / TM, 5);
    gemm_kernel<<<gg, 256>>>(w, w1, w2, N);

    combine_kernel<<<(N + 255) / 256, 256>>>(N);
    rowptr_kernel<<<(N + 1 + 255) / 256, 256>>>(rows, N, E);

    const long long threads = (long long)N * 32;
    attn_kernel<<<(unsigned)((threads + 255) / 256), 256>>>(cols, evals, out, N);
}